// round 2
// baseline (speedup 1.0000x reference)
#include <cuda_runtime.h>
#include <math.h>

#define BB    16
#define NN    1024
#define UU    64
#define F1    128          // 2U
#define MTOT  (BB*NN)      // 16384
#define MAXD  128
#define ALPHA 0.2f

// ---------------- scratch (device globals; no allocation) ----------------
__device__ float g_h1[MTOT * F1];       // 8 MB
__device__ float g_ssrc1[MTOT];
__device__ float g_sdst1[MTOT];
__device__ float g_rstate[MTOT * UU];   // 4 MB (r * state)
__device__ float g_z[MTOT * UU];        // 4 MB
__device__ float g_h2[MTOT * UU];       // 4 MB
__device__ float g_ssrc2[MTOT];
__device__ float g_sdst2[MTOT];
__device__ int   g_nbr[NN * MAXD];      // 512 KB
__device__ int   g_deg[NN];

// ---------------- build sparse neighbor lists (deterministic order) ------
__global__ void build_adj_kernel(const float* __restrict__ adj) {
    int warp = (blockIdx.x * blockDim.x + threadIdx.x) >> 5;
    int lane = threadIdx.x & 31;
    if (warp >= NN) return;
    int base = 0;
    for (int j0 = 0; j0 < NN; j0 += 32) {
        float v = adj[warp * NN + j0 + lane];
        unsigned mask = __ballot_sync(0xffffffffu, v > 0.0f);
        if (v > 0.0f) {
            int pos = base + __popc(mask & ((1u << lane) - 1u));
            if (pos < MAXD) g_nbr[warp * MAXD + pos] = j0 + lane;
        }
        base += __popc(mask);
    }
    if (lane == 0) g_deg[warp] = base < MAXD ? base : MAXD;
}

// ---------------- GEMM1: h1[m,128] = [X|state][m,128] @ W1[128,128] ------
// tile: 64 rows x 128 cols, K-tile 32. 256 threads, 8x4 microtile/thread.
__global__ void gemm1_kernel(const float* __restrict__ X,
                             const float* __restrict__ state,
                             const float* __restrict__ W1) {
    __shared__ float As[64][33];
    __shared__ float Bs[32][128];
    int tid = threadIdx.x;
    int cx = tid & 31;     // column group: cols cx*4 .. cx*4+3
    int ry = tid >> 5;     // row group:    rows ry*8 .. ry*8+7
    int m0 = blockIdx.x * 64;

    float acc[8][4];
    #pragma unroll
    for (int i = 0; i < 8; i++)
        #pragma unroll
        for (int c = 0; c < 4; c++) acc[i][c] = 0.0f;

    for (int kt = 0; kt < 4; kt++) {
        #pragma unroll
        for (int i = 0; i < 8; i++) {            // 2048 A elems
            int idx = tid + 256 * i;
            int rr = idx >> 5, kk = idx & 31;
            int m = m0 + rr;
            int k = kt * 32 + kk;
            As[rr][kk] = (k < 64) ? X[m * 64 + k] : state[m * 64 + k - 64];
        }
        #pragma unroll
        for (int i = 0; i < 16; i++) {           // 4096 B elems
            int idx = tid + 256 * i;
            int kk = idx >> 7, nn = idx & 127;
            Bs[kk][nn] = W1[(kt * 32 + kk) * 128 + nn];
        }
        __syncthreads();
        #pragma unroll
        for (int kk = 0; kk < 32; kk++) {
            float4 bv = *(const float4*)&Bs[kk][cx * 4];
            float a[8];
            #pragma unroll
            for (int i = 0; i < 8; i++) a[i] = As[ry * 8 + i][kk];
            #pragma unroll
            for (int i = 0; i < 8; i++) {
                acc[i][0] += a[i] * bv.x;
                acc[i][1] += a[i] * bv.y;
                acc[i][2] += a[i] * bv.z;
                acc[i][3] += a[i] * bv.w;
            }
        }
        __syncthreads();
    }
    #pragma unroll
    for (int i = 0; i < 8; i++) {
        float4 v = make_float4(acc[i][0], acc[i][1], acc[i][2], acc[i][3]);
        *(float4*)&g_h1[(size_t)(m0 + ry * 8 + i) * F1 + cx * 4] = v;
    }
}

// ---------------- per-node attention scalars: s = h . a ------------------
__global__ void s1_kernel(const float* __restrict__ a1) {
    int gw = (blockIdx.x * blockDim.x + threadIdx.x) >> 5;
    int lane = threadIdx.x & 31;
    if (gw >= MTOT) return;
    const float* h = g_h1 + (size_t)gw * F1;
    float ss = 0.0f, sd = 0.0f;
    #pragma unroll
    for (int c0 = 0; c0 < F1; c0 += 32) {
        float hv = h[c0 + lane];
        ss += hv * a1[c0 + lane];
        sd += hv * a1[F1 + c0 + lane];
    }
    #pragma unroll
    for (int o = 16; o; o >>= 1) {
        ss += __shfl_xor_sync(0xffffffffu, ss, o);
        sd += __shfl_xor_sync(0xffffffffu, sd, o);
    }
    if (lane == 0) { g_ssrc1[gw] = ss; g_sdst1[gw] = sd; }
}

__global__ void s2_kernel(const float* __restrict__ a2) {
    int gw = (blockIdx.x * blockDim.x + threadIdx.x) >> 5;
    int lane = threadIdx.x & 31;
    if (gw >= MTOT) return;
    const float* h = g_h2 + (size_t)gw * UU;
    float ss = 0.0f, sd = 0.0f;
    #pragma unroll
    for (int c0 = 0; c0 < UU; c0 += 32) {
        float hv = h[c0 + lane];
        ss += hv * a2[c0 + lane];
        sd += hv * a2[UU + c0 + lane];
    }
    #pragma unroll
    for (int o = 16; o; o >>= 1) {
        ss += __shfl_xor_sync(0xffffffffu, ss, o);
        sd += __shfl_xor_sync(0xffffffffu, sd, o);
    }
    if (lane == 0) { g_ssrc2[gw] = ss; g_sdst2[gw] = sd; }
}

// ---------------- attention layer 1 + sigmoid gate -----------------------
// one block per (b,i); 128 threads = 128 output channels
__global__ void att1_kernel(const float* __restrict__ state) {
    int bi = blockIdx.x;
    int b = bi >> 10;
    int i = bi & (NN - 1);
    int tid = threadIdx.x;
    __shared__ float w[MAXD];
    __shared__ int   js[MAXD];
    __shared__ float red[8];

    int deg = g_deg[i];
    float e = -3.0e38f;
    if (tid < deg) {
        int j = g_nbr[i * MAXD + tid];
        js[tid] = j;
        float x = g_ssrc1[b * NN + i] + g_sdst1[b * NN + j];
        e = (x > 0.0f) ? x : ALPHA * x;
    }
    float mx = e;
    #pragma unroll
    for (int o = 16; o; o >>= 1) mx = fmaxf(mx, __shfl_xor_sync(0xffffffffu, mx, o));
    if ((tid & 31) == 0) red[tid >> 5] = mx;
    __syncthreads();
    mx = fmaxf(fmaxf(red[0], red[1]), fmaxf(red[2], red[3]));

    float wv = (tid < deg) ? expf(e - mx) : 0.0f;
    w[tid] = wv;
    float sm = wv;
    #pragma unroll
    for (int o = 16; o; o >>= 1) sm += __shfl_xor_sync(0xffffffffu, sm, o);
    if ((tid & 31) == 0) red[4 + (tid >> 5)] = sm;
    __syncthreads();
    sm = red[4] + red[5] + red[6] + red[7];
    float inv = 1.0f / sm;

    float acc = 0.0f;
    const float* hbase = g_h1 + (size_t)b * NN * F1;
    for (int t = 0; t < deg; t++)
        acc += w[t] * hbase[js[t] * F1 + tid];
    acc *= inv;

    float gv = 1.0f / (1.0f + expf(-acc));   // sigmoid
    int m = b * NN + i;
    if (tid < UU) {
        g_rstate[m * UU + tid] = gv * state[m * UU + tid];   // r * state
    } else {
        g_z[m * UU + (tid - UU)] = gv;                        // z
    }
}

// ---------------- GEMM2: h2[m,64] = [X | r*state][m,128] @ W2[128,64] ----
// tile: 64 rows x 64 cols, K-tile 32. 256 threads, 4x4 microtile/thread.
__global__ void gemm2_kernel(const float* __restrict__ X,
                             const float* __restrict__ W2) {
    __shared__ float As[64][33];
    __shared__ float Bs[32][64];
    int tid = threadIdx.x;
    int cx = tid & 15;     // cols cx*4 .. cx*4+3
    int ry = tid >> 4;     // rows ry*4 .. ry*4+3
    int m0 = blockIdx.x * 64;

    float acc[4][4];
    #pragma unroll
    for (int i = 0; i < 4; i++)
        #pragma unroll
        for (int c = 0; c < 4; c++) acc[i][c] = 0.0f;

    for (int kt = 0; kt < 4; kt++) {
        #pragma unroll
        for (int i = 0; i < 8; i++) {            // 2048 A elems
            int idx = tid + 256 * i;
            int rr = idx >> 5, kk = idx & 31;
            int m = m0 + rr;
            int k = kt * 32 + kk;
            As[rr][kk] = (k < 64) ? X[m * 64 + k] : g_rstate[m * 64 + k - 64];
        }
        #pragma unroll
        for (int i = 0; i < 8; i++) {            // 2048 B elems
            int idx = tid + 256 * i;
            int kk = idx >> 6, nn = idx & 63;
            Bs[kk][nn] = W2[(kt * 32 + kk) * 64 + nn];
        }
        __syncthreads();
        #pragma unroll
        for (int kk = 0; kk < 32; kk++) {
            float4 bv = *(const float4*)&Bs[kk][cx * 4];
            float a[4];
            #pragma unroll
            for (int i = 0; i < 4; i++) a[i] = As[ry * 4 + i][kk];
            #pragma unroll
            for (int i = 0; i < 4; i++) {
                acc[i][0] += a[i] * bv.x;
                acc[i][1] += a[i] * bv.y;
                acc[i][2] += a[i] * bv.z;
                acc[i][3] += a[i] * bv.w;
            }
        }
        __syncthreads();
    }
    #pragma unroll
    for (int i = 0; i < 4; i++) {
        float4 v = make_float4(acc[i][0], acc[i][1], acc[i][2], acc[i][3]);
        *(float4*)&g_h2[(size_t)(m0 + ry * 4 + i) * UU + cx * 4] = v;
    }
}

// ---------------- attention layer 2 + tanh + GRU blend -------------------
__global__ void att2_kernel(const float* __restrict__ state,
                            float* __restrict__ out) {
    int bi = blockIdx.x;
    int b = bi >> 10;
    int i = bi & (NN - 1);
    int tid = threadIdx.x;
    __shared__ float w[MAXD];
    __shared__ int   js[MAXD];
    __shared__ float red[8];

    int deg = g_deg[i];
    float e = -3.0e38f;
    if (tid < deg) {
        int j = g_nbr[i * MAXD + tid];
        js[tid] = j;
        float x = g_ssrc2[b * NN + i] + g_sdst2[b * NN + j];
        e = (x > 0.0f) ? x : ALPHA * x;
    }
    float mx = e;
    #pragma unroll
    for (int o = 16; o; o >>= 1) mx = fmaxf(mx, __shfl_xor_sync(0xffffffffu, mx, o));
    if ((tid & 31) == 0) red[tid >> 5] = mx;
    __syncthreads();
    mx = fmaxf(fmaxf(red[0], red[1]), fmaxf(red[2], red[3]));

    float wv = (tid < deg) ? expf(e - mx) : 0.0f;
    w[tid] = wv;
    float sm = wv;
    #pragma unroll
    for (int o = 16; o; o >>= 1) sm += __shfl_xor_sync(0xffffffffu, sm, o);
    if ((tid & 31) == 0) red[4 + (tid >> 5)] = sm;
    __syncthreads();
    sm = red[4] + red[5] + red[6] + red[7];
    float inv = 1.0f / sm;

    if (tid < UU) {
        float acc = 0.0f;
        const float* hbase = g_h2 + (size_t)b * NN * UU;
        for (int t = 0; t < deg; t++)
            acc += w[t] * hbase[js[t] * UU + tid];
        acc *= inv;
        float ht = tanhf(acc);
        int m = b * NN + i;
        float z = g_z[m * UU + tid];
        out[m * UU + tid] = z * state[m * UU + tid] + (1.0f - z) * ht;
    }
}

// ---------------- launch -------------------------------------------------
extern "C" void kernel_launch(void* const* d_in, const int* in_sizes, int n_in,
                              void* d_out, int out_size) {
    const float* X     = (const float*)d_in[0];
    const float* state = (const float*)d_in[1];
    const float* adj   = (const float*)d_in[2];
    const float* W1    = (const float*)d_in[3];
    const float* a1    = (const float*)d_in[4];
    const float* W2    = (const float*)d_in[5];
    const float* a2    = (const float*)d_in[6];
    float* out = (float*)d_out;

    build_adj_kernel<<<NN / 8, 256>>>(adj);               // 1024 warps
    gemm1_kernel<<<MTOT / 64, 256>>>(X, state, W1);
    s1_kernel<<<MTOT / 8, 256>>>(a1);
    att1_kernel<<<MTOT, 128>>>(state);
    gemm2_kernel<<<MTOT / 64, 256>>>(X, W2);
    s2_kernel<<<MTOT / 8, 256>>>(a2);
    att2_kernel<<<MTOT, 128>>>(state, out);
}

// round 3
// speedup vs baseline: 1.2087x; 1.2087x over previous
#include <cuda_runtime.h>
#include <cuda_fp16.h>
#include <math.h>

#define BB    16
#define NN    1024
#define UU    64
#define F1    128          // 2U
#define MTOT  (BB*NN)      // 16384
#define MAXD  128
#define ALPHA 0.2f

// ---------------- scratch (device globals; no allocation) ----------------
__device__ __half g_h1h[MTOT * F1];     // 4 MB  fp16 gather payload, layer 1
__device__ __half g_h2h[MTOT * UU];     // 2 MB  fp16 gather payload, layer 2
__device__ float  g_ssrc1[MTOT];
__device__ float  g_sdst1[MTOT];
__device__ float  g_ssrc2[MTOT];
__device__ float  g_sdst2[MTOT];
__device__ float  g_rstate[MTOT * UU];  // 4 MB (r * state)
__device__ float  g_z[MTOT * UU];       // 4 MB
__device__ int    g_nbr[NN * MAXD];     // 512 KB
__device__ int    g_deg[NN];

// ---------------- build sparse neighbor lists (deterministic order) ------
__global__ void build_adj_kernel(const float* __restrict__ adj) {
    int warp = (blockIdx.x * blockDim.x + threadIdx.x) >> 5;
    int lane = threadIdx.x & 31;
    if (warp >= NN) return;
    int base = 0;
    for (int j0 = 0; j0 < NN; j0 += 32) {
        float v = adj[warp * NN + j0 + lane];
        unsigned mask = __ballot_sync(0xffffffffu, v > 0.0f);
        if (v > 0.0f) {
            int pos = base + __popc(mask & ((1u << lane) - 1u));
            if (pos < MAXD) g_nbr[warp * MAXD + pos] = j0 + lane;
        }
        base += __popc(mask);
    }
    if (lane == 0) g_deg[warp] = base < MAXD ? base : MAXD;
}

// ---------------- GEMM1: h1[m,128] = [X|state][m,128] @ W1[128,128] ------
// fused: fp16 store of h1 + per-row attention scalars s_src/s_dst (fp32)
__global__ void gemm1_kernel(const float* __restrict__ X,
                             const float* __restrict__ state,
                             const float* __restrict__ W1,
                             const float* __restrict__ a1) {
    __shared__ float As[64][33];
    __shared__ float Bs[32][128];
    int tid = threadIdx.x;
    int cx = tid & 31;     // column group: cols cx*4 .. cx*4+3
    int ry = tid >> 5;     // row group:    rows ry*8 .. ry*8+7 (== warp id)
    int m0 = blockIdx.x * 64;

    float acc[8][4];
    #pragma unroll
    for (int i = 0; i < 8; i++)
        #pragma unroll
        for (int c = 0; c < 4; c++) acc[i][c] = 0.0f;

    for (int kt = 0; kt < 4; kt++) {
        #pragma unroll
        for (int i = 0; i < 8; i++) {            // 2048 A elems
            int idx = tid + 256 * i;
            int rr = idx >> 5, kk = idx & 31;
            int m = m0 + rr;
            int k = kt * 32 + kk;
            As[rr][kk] = (k < 64) ? X[m * 64 + k] : state[m * 64 + k - 64];
        }
        #pragma unroll
        for (int i = 0; i < 16; i++) {           // 4096 B elems
            int idx = tid + 256 * i;
            int kk = idx >> 7, nn = idx & 127;
            Bs[kk][nn] = W1[(kt * 32 + kk) * 128 + nn];
        }
        __syncthreads();
        #pragma unroll
        for (int kk = 0; kk < 32; kk++) {
            float4 bv = *(const float4*)&Bs[kk][cx * 4];
            float a[8];
            #pragma unroll
            for (int i = 0; i < 8; i++) a[i] = As[ry * 8 + i][kk];
            #pragma unroll
            for (int i = 0; i < 8; i++) {
                acc[i][0] += a[i] * bv.x;
                acc[i][1] += a[i] * bv.y;
                acc[i][2] += a[i] * bv.z;
                acc[i][3] += a[i] * bv.w;
            }
        }
        __syncthreads();
    }

    // epilogue: fp16 store + fused s = h . a (warp = one row group, lanes = cx)
    float avs[4], avd[4];
    #pragma unroll
    for (int c = 0; c < 4; c++) {
        avs[c] = a1[cx * 4 + c];
        avd[c] = a1[F1 + cx * 4 + c];
    }
    #pragma unroll
    for (int i = 0; i < 8; i++) {
        int m = m0 + ry * 8 + i;
        __half2 p0 = __floats2half2_rn(acc[i][0], acc[i][1]);
        __half2 p1 = __floats2half2_rn(acc[i][2], acc[i][3]);
        __half2* dst = (__half2*)&g_h1h[(size_t)m * F1 + cx * 4];
        dst[0] = p0;
        dst[1] = p1;
        float ps = acc[i][0]*avs[0] + acc[i][1]*avs[1] + acc[i][2]*avs[2] + acc[i][3]*avs[3];
        float pd = acc[i][0]*avd[0] + acc[i][1]*avd[1] + acc[i][2]*avd[2] + acc[i][3]*avd[3];
        #pragma unroll
        for (int o = 16; o; o >>= 1) {
            ps += __shfl_xor_sync(0xffffffffu, ps, o);
            pd += __shfl_xor_sync(0xffffffffu, pd, o);
        }
        if (cx == 0) { g_ssrc1[m] = ps; g_sdst1[m] = pd; }
    }
}

// ---------------- attention layer 1 + sigmoid gate -----------------------
// one block per (b,i); 64 threads; each thread owns 2 channels via half2
__global__ void att1_kernel(const float* __restrict__ state) {
    int bi = blockIdx.x;
    int b = bi >> 10;
    int i = bi & (NN - 1);
    int tid = threadIdx.x;          // 0..63
    __shared__ float w[MAXD];
    __shared__ int   js[MAXD];
    __shared__ float red[4];

    int deg = g_deg[i];
    float si = g_ssrc1[b * NN + i];
    float e0 = -3.0e38f, e1 = -3.0e38f;
    if (tid < deg) {
        int j = g_nbr[i * MAXD + tid];
        js[tid] = j;
        float x = si + g_sdst1[b * NN + j];
        e0 = (x > 0.0f) ? x : ALPHA * x;
    }
    int t1 = tid + 64;
    if (t1 < deg) {
        int j = g_nbr[i * MAXD + t1];
        js[t1] = j;
        float x = si + g_sdst1[b * NN + j];
        e1 = (x > 0.0f) ? x : ALPHA * x;
    }
    float mx = fmaxf(e0, e1);
    #pragma unroll
    for (int o = 16; o; o >>= 1) mx = fmaxf(mx, __shfl_xor_sync(0xffffffffu, mx, o));
    if ((tid & 31) == 0) red[tid >> 5] = mx;
    __syncthreads();
    mx = fmaxf(red[0], red[1]);

    float w0 = (tid < deg) ? expf(e0 - mx) : 0.0f;
    float w1 = (t1  < deg) ? expf(e1 - mx) : 0.0f;
    w[tid] = w0;
    if (t1 < deg) w[t1] = w1;
    float sm = w0 + w1;
    #pragma unroll
    for (int o = 16; o; o >>= 1) sm += __shfl_xor_sync(0xffffffffu, sm, o);
    if ((tid & 31) == 0) red[2 + (tid >> 5)] = sm;
    __syncthreads();                 // also publishes w[], js[]
    float inv = 1.0f / (red[2] + red[3]);

    // gather: channels 2*tid, 2*tid+1 over fp16 payload
    const __half2* hb = (const __half2*)g_h1h + (size_t)b * NN * 64 + tid;
    float ax = 0.0f, ay = 0.0f;
    int t = 0;
    for (; t + 4 <= deg; t += 4) {
        float ww0 = w[t],  ww1 = w[t+1], ww2 = w[t+2], ww3 = w[t+3];
        int ja = js[t], jb = js[t+1], jc = js[t+2], jd = js[t+3];
        float2 f0 = __half22float2(hb[(size_t)ja * 64]);
        float2 f1 = __half22float2(hb[(size_t)jb * 64]);
        float2 f2 = __half22float2(hb[(size_t)jc * 64]);
        float2 f3 = __half22float2(hb[(size_t)jd * 64]);
        ax += ww0*f0.x + ww1*f1.x + ww2*f2.x + ww3*f3.x;
        ay += ww0*f0.y + ww1*f1.y + ww2*f2.y + ww3*f3.y;
    }
    for (; t < deg; t++) {
        float ww = w[t];
        float2 f = __half22float2(hb[(size_t)js[t] * 64]);
        ax += ww * f.x;
        ay += ww * f.y;
    }
    ax *= inv; ay *= inv;
    float g0 = 1.0f / (1.0f + expf(-ax));
    float g1 = 1.0f / (1.0f + expf(-ay));

    int m = b * NN + i;
    if (tid < 32) {                  // channels < 64 -> r * state
        float2 st = *(const float2*)&state[(size_t)m * UU + 2 * tid];
        float2 r2 = make_float2(g0 * st.x, g1 * st.y);
        *(float2*)&g_rstate[(size_t)m * UU + 2 * tid] = r2;
    } else {                         // channels >= 64 -> z
        float2 z2 = make_float2(g0, g1);
        *(float2*)&g_z[(size_t)m * UU + 2 * (tid - 32)] = z2;
    }
}

// ---------------- GEMM2: h2[m,64] = [X | r*state][m,128] @ W2[128,64] ----
// fused: fp16 store of h2 + per-row attention scalars (fp32)
__global__ void gemm2_kernel(const float* __restrict__ X,
                             const float* __restrict__ W2,
                             const float* __restrict__ a2) {
    __shared__ float As[64][33];
    __shared__ float Bs[32][64];
    int tid = threadIdx.x;
    int cx = tid & 15;     // cols cx*4 .. cx*4+3
    int ry = tid >> 4;     // rows ry*4 .. ry*4+3
    int m0 = blockIdx.x * 64;

    float acc[4][4];
    #pragma unroll
    for (int i = 0; i < 4; i++)
        #pragma unroll
        for (int c = 0; c < 4; c++) acc[i][c] = 0.0f;

    for (int kt = 0; kt < 4; kt++) {
        #pragma unroll
        for (int i = 0; i < 8; i++) {            // 2048 A elems
            int idx = tid + 256 * i;
            int rr = idx >> 5, kk = idx & 31;
            int m = m0 + rr;
            int k = kt * 32 + kk;
            As[rr][kk] = (k < 64) ? X[m * 64 + k] : g_rstate[m * 64 + k - 64];
        }
        #pragma unroll
        for (int i = 0; i < 8; i++) {            // 2048 B elems
            int idx = tid + 256 * i;
            int kk = idx >> 6, nn = idx & 63;
            Bs[kk][nn] = W2[(kt * 32 + kk) * 64 + nn];
        }
        __syncthreads();
        #pragma unroll
        for (int kk = 0; kk < 32; kk++) {
            float4 bv = *(const float4*)&Bs[kk][cx * 4];
            float a[4];
            #pragma unroll
            for (int i = 0; i < 4; i++) a[i] = As[ry * 4 + i][kk];
            #pragma unroll
            for (int i = 0; i < 4; i++) {
                acc[i][0] += a[i] * bv.x;
                acc[i][1] += a[i] * bv.y;
                acc[i][2] += a[i] * bv.z;
                acc[i][3] += a[i] * bv.w;
            }
        }
        __syncthreads();
    }

    // epilogue: fp16 store + fused s = h . a
    // warp holds two 16-lane row groups; xor offsets {8,4,2,1} stay in-group
    float avs[4], avd[4];
    #pragma unroll
    for (int c = 0; c < 4; c++) {
        avs[c] = a2[cx * 4 + c];
        avd[c] = a2[UU + cx * 4 + c];
    }
    #pragma unroll
    for (int i = 0; i < 4; i++) {
        int m = m0 + ry * 4 + i;
        __half2 p0 = __floats2half2_rn(acc[i][0], acc[i][1]);
        __half2 p1 = __floats2half2_rn(acc[i][2], acc[i][3]);
        __half2* dst = (__half2*)&g_h2h[(size_t)m * UU + cx * 4];
        dst[0] = p0;
        dst[1] = p1;
        float ps = acc[i][0]*avs[0] + acc[i][1]*avs[1] + acc[i][2]*avs[2] + acc[i][3]*avs[3];
        float pd = acc[i][0]*avd[0] + acc[i][1]*avd[1] + acc[i][2]*avd[2] + acc[i][3]*avd[3];
        #pragma unroll
        for (int o = 8; o; o >>= 1) {
            ps += __shfl_xor_sync(0xffffffffu, ps, o);
            pd += __shfl_xor_sync(0xffffffffu, pd, o);
        }
        if (cx == 0) { g_ssrc2[m] = ps; g_sdst2[m] = pd; }
    }
}

// ---------------- attention layer 2 + tanh + GRU blend -------------------
// 64 threads: all do scores; threads 0..31 gather 64 channels via half2
__global__ void att2_kernel(const float* __restrict__ state,
                            float* __restrict__ out) {
    int bi = blockIdx.x;
    int b = bi >> 10;
    int i = bi & (NN - 1);
    int tid = threadIdx.x;          // 0..63
    __shared__ float w[MAXD];
    __shared__ int   js[MAXD];
    __shared__ float red[4];

    int deg = g_deg[i];
    float si = g_ssrc2[b * NN + i];
    float e0 = -3.0e38f, e1 = -3.0e38f;
    if (tid < deg) {
        int j = g_nbr[i * MAXD + tid];
        js[tid] = j;
        float x = si + g_sdst2[b * NN + j];
        e0 = (x > 0.0f) ? x : ALPHA * x;
    }
    int t1 = tid + 64;
    if (t1 < deg) {
        int j = g_nbr[i * MAXD + t1];
        js[t1] = j;
        float x = si + g_sdst2[b * NN + j];
        e1 = (x > 0.0f) ? x : ALPHA * x;
    }
    float mx = fmaxf(e0, e1);
    #pragma unroll
    for (int o = 16; o; o >>= 1) mx = fmaxf(mx, __shfl_xor_sync(0xffffffffu, mx, o));
    if ((tid & 31) == 0) red[tid >> 5] = mx;
    __syncthreads();
    mx = fmaxf(red[0], red[1]);

    float w0 = (tid < deg) ? expf(e0 - mx) : 0.0f;
    float w1 = (t1  < deg) ? expf(e1 - mx) : 0.0f;
    w[tid] = w0;
    if (t1 < deg) w[t1] = w1;
    float sm = w0 + w1;
    #pragma unroll
    for (int o = 16; o; o >>= 1) sm += __shfl_xor_sync(0xffffffffu, sm, o);
    if ((tid & 31) == 0) red[2 + (tid >> 5)] = sm;
    __syncthreads();
    float inv = 1.0f / (red[2] + red[3]);

    if (tid < 32) {
        const __half2* hb = (const __half2*)g_h2h + (size_t)b * NN * 32 + tid;
        float ax = 0.0f, ay = 0.0f;
        int t = 0;
        for (; t + 4 <= deg; t += 4) {
            float ww0 = w[t], ww1 = w[t+1], ww2 = w[t+2], ww3 = w[t+3];
            int ja = js[t], jb = js[t+1], jc = js[t+2], jd = js[t+3];
            float2 f0 = __half22float2(hb[(size_t)ja * 32]);
            float2 f1 = __half22float2(hb[(size_t)jb * 32]);
            float2 f2 = __half22float2(hb[(size_t)jc * 32]);
            float2 f3 = __half22float2(hb[(size_t)jd * 32]);
            ax += ww0*f0.x + ww1*f1.x + ww2*f2.x + ww3*f3.x;
            ay += ww0*f0.y + ww1*f1.y + ww2*f2.y + ww3*f3.y;
        }
        for (; t < deg; t++) {
            float ww = w[t];
            float2 f = __half22float2(hb[(size_t)js[t] * 32]);
            ax += ww * f.x;
            ay += ww * f.y;
        }
        ax *= inv; ay *= inv;
        float h0 = tanhf(ax);
        float h1v = tanhf(ay);

        int m = b * NN + i;
        float2 st = *(const float2*)&state[(size_t)m * UU + 2 * tid];
        float2 z2 = *(const float2*)&g_z[(size_t)m * UU + 2 * tid];
        float2 o2;
        o2.x = z2.x * st.x + (1.0f - z2.x) * h0;
        o2.y = z2.y * st.y + (1.0f - z2.y) * h1v;
        *(float2*)&out[(size_t)m * UU + 2 * tid] = o2;
    }
}

// ---------------- launch -------------------------------------------------
extern "C" void kernel_launch(void* const* d_in, const int* in_sizes, int n_in,
                              void* d_out, int out_size) {
    const float* X     = (const float*)d_in[0];
    const float* state = (const float*)d_in[1];
    const float* adj   = (const float*)d_in[2];
    const float* W1    = (const float*)d_in[3];
    const float* a1    = (const float*)d_in[4];
    const float* W2    = (const float*)d_in[5];
    const float* a2    = (const float*)d_in[6];
    float* out = (float*)d_out;

    build_adj_kernel<<<NN / 8, 256>>>(adj);
    gemm1_kernel<<<MTOT / 64, 256>>>(X, state, W1, a1);
    att1_kernel<<<MTOT, 64>>>(state);
    gemm2_kernel<<<MTOT / 64, 256>>>(X, W2, a2);
    att2_kernel<<<MTOT, 64>>>(state, out);
}